// round 7
// baseline (speedup 1.0000x reference)
#include <cuda_runtime.h>
#include <cstdint>

// AdEx neuron scan, T=2048, N=32768. spikes[t,n] in f32 {0,1}.
// w == 0 identically (A=0, B=0, w0=0) -> dropped.
// Fast path (valid while V <= -20 mV, where 2*exp((V-0.6)/2) < 7e-5 cannot
// affect spiking): V' = 0.995*V + 0.005*(I - 70), spike = 0.
// Rare path: exact per-tile redo (exp + spike/reset).
//
// R7 vs R6: fast-path stores replaced by block-cooperative STG.128 zero-fill
// of the whole tile, selected block-uniformly AFTER the scan via SMEM flags +
// one barrier. Exactly one of {zero-fill, exact-redo-stores} runs per tile,
// so no store-ordering hazard. Cuts LSU store-issue cycles ~40% (2048 STG.32
// -> 512 STG.128 per thread) which was the binding resource at R6's 72.8%
// DRAM. DEPTH 4->5 for extra cp.async slack.

#define AX_N  32768
#define BLK   64              // threads per block == columns per block
#define RTILE 32              // rows (timesteps) per tile
#define DEPTH 5               // SMEM ring buffers
#define TILE_ELEMS (RTILE * BLK)   // 2048 floats = 8KB

__device__ __forceinline__ void issue_tile(const float* __restrict__ I,
                                           int tile, int slot, int n0, int tid,
                                           float (*buf)[TILE_ELEMS]) {
    const float* gbase = I + (size_t)tile * RTILE * AX_N + n0;
    uint32_t sbase = (uint32_t)__cvta_generic_to_shared(&buf[slot][0]);
    #pragma unroll
    for (int j = 0; j < 8; ++j) {
        const int idx = tid + j * BLK;   // 0..511
        const int r = idx >> 4;          // 0..31
        const int c = idx & 15;          // 0..15
        const float* g = gbase + (size_t)r * AX_N + c * 4;
        const uint32_t s = sbase + (uint32_t)(r * BLK + c * 4) * 4u;
        asm volatile("cp.async.cg.shared.global [%0], [%1], 16;\n"
                     :: "r"(s), "l"(g));
    }
    asm volatile("cp.async.commit_group;\n" ::: "memory");
}

__global__ void __launch_bounds__(BLK, 4)
adex_kernel(const float* __restrict__ I, float* __restrict__ S, int T) {
    __shared__ __align__(128) float buf[DEPTH][TILE_ELEMS];
    __shared__ int rare_flag[2];         // one per warp

    const int tid = threadIdx.x;
    const int wid = tid >> 5;
    const int lane = tid & 31;
    const int n0 = blockIdx.x * BLK;
    const int n = n0 + tid;

    float* op = S + n;
    float V = -70.0f;   // E_L

    const int ntiles = T / RTILE;

    // Prologue: DEPTH-1 tiles in flight.
    for (int p = 0; p < DEPTH - 1 && p < ntiles; ++p)
        issue_tile(I, p, p, n0, tid, buf);

    for (int i = 0; i < ntiles; ++i) {
        asm volatile("cp.async.wait_group %0;\n" :: "n"(DEPTH - 2) : "memory");
        __syncthreads();   // tile i visible; prior tile's stores/flags done

        if (i + DEPTH - 1 < ntiles)
            issue_tile(I, i + DEPTH - 1, (i + DEPTH - 1) % DEPTH, n0, tid, buf);

        const float* tb = buf[i % DEPTH];
        const int t0 = i * RTILE;

        // Scan (registers only, no stores).
        const float Vs = V;
        float v = V;
        float m = V;
        #pragma unroll
        for (int r = 0; r < RTILE; ++r) {
            const float iv = tb[r * BLK + tid];
            v = fmaf(0.995f, v, fmaf(0.005f, iv, -0.35f));
            m = fmaxf(m, v);
        }
        const bool rare = __any_sync(0xFFFFFFFFu, m > -20.0f);
        if (lane == 0) rare_flag[wid] = rare ? 1 : 0;
        __syncthreads();
        const bool block_rare = (rare_flag[0] | rare_flag[1]) != 0;
        // (next write to rare_flag is ordered behind this read by the
        //  wait+__syncthreads at the top of the next iteration)

        if (!block_rare) {
            // Cooperative zero-fill of rows [t0, t0+RTILE) x cols [n0, n0+64):
            // 512 float4, 8 per thread, fully coalesced STG.128.
            const float4 z = make_float4(0.f, 0.f, 0.f, 0.f);
            #pragma unroll
            for (int j = 0; j < 8; ++j) {
                const int idx = tid + j * BLK;
                const int row = idx >> 4;      // 0..31
                const int col4 = idx & 15;     // 0..15
                __stcs((float4*)(S + (size_t)(t0 + row) * AX_N + n0) + col4, z);
            }
            V = v;
        } else {
            // Exact AdEx redo for the whole tile (rare; block-uniform).
            v = Vs;
            #pragma unroll 1
            for (int r = 0; r < RTILE; ++r) {
                const float iv = tb[r * BLK + tid];
                const float e = 2.0f * expf((v - 0.6f) * 0.5f);
                float Vn = v + 0.005f * ((-70.0f - v) + e + iv);
                float s = 0.0f;
                if (Vn >= 30.0f) { s = 1.0f; Vn = -65.0f; }
                v = Vn;
                __stcs(op + (size_t)(t0 + r) * AX_N, s);
            }
            V = v;
        }
    }

    // Scalar tail (T % RTILE != 0): always-exact path, direct global loads.
    for (int t = ntiles * RTILE; t < T; ++t) {
        const float iv = __ldcs(I + (size_t)t * AX_N + n);
        const float e = 2.0f * expf((V - 0.6f) * 0.5f);
        float Vn = V + 0.005f * ((-70.0f - V) + e + iv);
        float s = 0.0f;
        if (Vn >= 30.0f) { s = 1.0f; Vn = -65.0f; }
        V = Vn;
        __stcs(op + (size_t)t * AX_N, s);
    }
}

extern "C" void kernel_launch(void* const* d_in, const int* in_sizes, int n_in,
                              void* d_out, int out_size) {
    const float* I = (const float*)d_in[0];
    float* S = (float*)d_out;
    const int T = in_sizes[0] / AX_N;   // 2048
    adex_kernel<<<AX_N / BLK, BLK>>>(I, S, T);   // 512 blocks x 64 threads
}

// round 8
// speedup vs baseline: 1.0036x; 1.0036x over previous
#include <cuda_runtime.h>
#include <cstdint>

// AdEx neuron scan, T=2048, N=32768. spikes[t,n] in f32 {0,1}.
// w == 0 identically (A=0, B=0, w0=0) -> dropped.
// Fast path (valid while V <= -20 mV, where 2*exp((V-0.6)/2) < 7e-5 cannot
// affect spiking): V' = 0.995*V + 0.005*(I - 70), spike = 0.
// Rare path: exact per-tile redo (exp + spike/reset).
//
// R7 vs R6: fast-path stores replaced by block-cooperative STG.128 zero-fill
// of the whole tile, selected block-uniformly AFTER the scan via SMEM flags +
// one barrier. Exactly one of {zero-fill, exact-redo-stores} runs per tile,
// so no store-ordering hazard. Cuts LSU store-issue cycles ~40% (2048 STG.32
// -> 512 STG.128 per thread) which was the binding resource at R6's 72.8%
// DRAM. DEPTH 4->5 for extra cp.async slack.

#define AX_N  32768
#define BLK   64              // threads per block == columns per block
#define RTILE 32              // rows (timesteps) per tile
#define DEPTH 5               // SMEM ring buffers
#define TILE_ELEMS (RTILE * BLK)   // 2048 floats = 8KB

__device__ __forceinline__ void issue_tile(const float* __restrict__ I,
                                           int tile, int slot, int n0, int tid,
                                           float (*buf)[TILE_ELEMS]) {
    const float* gbase = I + (size_t)tile * RTILE * AX_N + n0;
    uint32_t sbase = (uint32_t)__cvta_generic_to_shared(&buf[slot][0]);
    #pragma unroll
    for (int j = 0; j < 8; ++j) {
        const int idx = tid + j * BLK;   // 0..511
        const int r = idx >> 4;          // 0..31
        const int c = idx & 15;          // 0..15
        const float* g = gbase + (size_t)r * AX_N + c * 4;
        const uint32_t s = sbase + (uint32_t)(r * BLK + c * 4) * 4u;
        asm volatile("cp.async.cg.shared.global [%0], [%1], 16;\n"
                     :: "r"(s), "l"(g));
    }
    asm volatile("cp.async.commit_group;\n" ::: "memory");
}

__global__ void __launch_bounds__(BLK, 4)
adex_kernel(const float* __restrict__ I, float* __restrict__ S, int T) {
    __shared__ __align__(128) float buf[DEPTH][TILE_ELEMS];
    __shared__ int rare_flag[2];         // one per warp

    const int tid = threadIdx.x;
    const int wid = tid >> 5;
    const int lane = tid & 31;
    const int n0 = blockIdx.x * BLK;
    const int n = n0 + tid;

    float* op = S + n;
    float V = -70.0f;   // E_L

    const int ntiles = T / RTILE;

    // Prologue: DEPTH-1 tiles in flight.
    for (int p = 0; p < DEPTH - 1 && p < ntiles; ++p)
        issue_tile(I, p, p, n0, tid, buf);

    for (int i = 0; i < ntiles; ++i) {
        asm volatile("cp.async.wait_group %0;\n" :: "n"(DEPTH - 2) : "memory");
        __syncthreads();   // tile i visible; prior tile's stores/flags done

        if (i + DEPTH - 1 < ntiles)
            issue_tile(I, i + DEPTH - 1, (i + DEPTH - 1) % DEPTH, n0, tid, buf);

        const float* tb = buf[i % DEPTH];
        const int t0 = i * RTILE;

        // Scan (registers only, no stores).
        const float Vs = V;
        float v = V;
        float m = V;
        #pragma unroll
        for (int r = 0; r < RTILE; ++r) {
            const float iv = tb[r * BLK + tid];
            v = fmaf(0.995f, v, fmaf(0.005f, iv, -0.35f));
            m = fmaxf(m, v);
        }
        const bool rare = __any_sync(0xFFFFFFFFu, m > -20.0f);
        if (lane == 0) rare_flag[wid] = rare ? 1 : 0;
        __syncthreads();
        const bool block_rare = (rare_flag[0] | rare_flag[1]) != 0;
        // (next write to rare_flag is ordered behind this read by the
        //  wait+__syncthreads at the top of the next iteration)

        if (!block_rare) {
            // Cooperative zero-fill of rows [t0, t0+RTILE) x cols [n0, n0+64):
            // 512 float4, 8 per thread, fully coalesced STG.128.
            const float4 z = make_float4(0.f, 0.f, 0.f, 0.f);
            #pragma unroll
            for (int j = 0; j < 8; ++j) {
                const int idx = tid + j * BLK;
                const int row = idx >> 4;      // 0..31
                const int col4 = idx & 15;     // 0..15
                __stcs((float4*)(S + (size_t)(t0 + row) * AX_N + n0) + col4, z);
            }
            V = v;
        } else {
            // Exact AdEx redo for the whole tile (rare; block-uniform).
            v = Vs;
            #pragma unroll 1
            for (int r = 0; r < RTILE; ++r) {
                const float iv = tb[r * BLK + tid];
                const float e = 2.0f * expf((v - 0.6f) * 0.5f);
                float Vn = v + 0.005f * ((-70.0f - v) + e + iv);
                float s = 0.0f;
                if (Vn >= 30.0f) { s = 1.0f; Vn = -65.0f; }
                v = Vn;
                __stcs(op + (size_t)(t0 + r) * AX_N, s);
            }
            V = v;
        }
    }

    // Scalar tail (T % RTILE != 0): always-exact path, direct global loads.
    for (int t = ntiles * RTILE; t < T; ++t) {
        const float iv = __ldcs(I + (size_t)t * AX_N + n);
        const float e = 2.0f * expf((V - 0.6f) * 0.5f);
        float Vn = V + 0.005f * ((-70.0f - V) + e + iv);
        float s = 0.0f;
        if (Vn >= 30.0f) { s = 1.0f; Vn = -65.0f; }
        V = Vn;
        __stcs(op + (size_t)t * AX_N, s);
    }
}

extern "C" void kernel_launch(void* const* d_in, const int* in_sizes, int n_in,
                              void* d_out, int out_size) {
    const float* I = (const float*)d_in[0];
    float* S = (float*)d_out;
    const int T = in_sizes[0] / AX_N;   // 2048
    adex_kernel<<<AX_N / BLK, BLK>>>(I, S, T);   // 512 blocks x 64 threads
}